// round 15
// baseline (speedup 1.0000x reference)
#include <cuda_runtime.h>
#include <cuda_fp16.h>
#include <math.h>
#include <stdint.h>

#define NENT 150000
#define NRELN 500
#define HD 128
#define DEG 32
#define TOPK 10
#define NB 1172   // ceil(NENT/128)

// -------- scratch (device globals; no allocation allowed) --------
__device__ uint32_t g_neighh[150016 * 64];  // neigh as half2 pairs
__device__ uint32_t g_hnodeh[150016 * 64];  // h_node as half2 pairs
__device__ uint32_t g_hrelh[512 * 64];      // h_rel  as half2 pairs
__device__ float g_ssrc[150016];
__device__ float g_sdst[150016];
__device__ float g_srel[512];
__device__ float g_wv[3][128];              // W@a1, W@a2, Wr@a3 (exact score vectors)
// pre-transposed + swizzled fp16-split weight images: [matrix][hi 32KB | lo 32KB]
__device__ __align__(16) unsigned char g_Bimg[3][65536];

// ================= helpers =================
__device__ __forceinline__ uint32_t smem_u32(const void* p) {
    uint32_t a;
    asm("{ .reg .u64 t; cvta.to.shared.u64 t, %1; cvt.u32.u64 %0, t; }" : "=r"(a) : "l"(p));
    return a;
}
__device__ __forceinline__ void ldsm_x4(uint32_t* r, uint32_t addr) {
    asm volatile("ldmatrix.sync.aligned.m8n8.x4.shared.b16 {%0,%1,%2,%3}, [%4];"
                 : "=r"(r[0]), "=r"(r[1]), "=r"(r[2]), "=r"(r[3]) : "r"(addr));
}
__device__ __forceinline__ void mma_f16(float* d, const uint32_t* a, uint32_t b0, uint32_t b1) {
    asm volatile(
        "mma.sync.aligned.m16n8k16.row.col.f32.f16.f16.f32 "
        "{%0,%1,%2,%3}, {%4,%5,%6,%7}, {%8,%9}, {%0,%1,%2,%3};"
        : "+f"(d[0]), "+f"(d[1]), "+f"(d[2]), "+f"(d[3])
        : "r"(a[0]), "r"(a[1]), "r"(a[2]), "r"(a[3]), "r"(b0), "r"(b1));
}
__device__ __forceinline__ void h_split(float v, __half& h, __half& l) {
    h = __float2half_rn(v);
    l = __float2half_rn(v - __half2float(h));
}
__device__ __forceinline__ uint32_t pack2(__half a, __half b) {
    __half2 t;
    t.x = a; t.y = b;
    return *reinterpret_cast<uint32_t*>(&t);
}
__device__ __forceinline__ __half2 u2h2(uint32_t u) {
    return *reinterpret_cast<__half2*>(&u);
}
// tile layout: row-major rows of 128 f16 (256B = 16 units of 16B), unit XOR-swizzled
__device__ __forceinline__ uint32_t img_off(int n, int k) {
    return (uint32_t)(n * 256 + ((((k >> 3) ^ (n & 7))) << 4) + (k & 7) * 2);
}

// ---------------------------------------------------------------
// prep: blockIdx 0..2 build weight images; blockIdx 3 computes the
// exact score vectors w1 = W@a1, w2 = W@a2, w3 = Wr@a3 (fp32).
// ---------------------------------------------------------------
__global__ void __launch_bounds__(256) prep_kernel(const float* __restrict__ W,
                                                   const float* __restrict__ Wr,
                                                   const float* __restrict__ Nw,
                                                   const float* __restrict__ a) {
    if (blockIdx.x == 3) {
        int k = threadIdx.x;
        if (k < 128) {
            float d1 = 0.f, d2 = 0.f;
            for (int n = 0; n < 128; ++n) {
                float wv = W[k * 128 + n];
                d1 += wv * a[n];
                d2 += wv * a[128 + n];
            }
            g_wv[0][k] = d1;
            g_wv[1][k] = d2;
        } else {
            int kk = k - 128;
            float d3 = 0.f;
            for (int n = 0; n < 128; ++n) d3 += Wr[kk * 128 + n] * a[256 + n];
            g_wv[2][kk] = d3;
        }
        return;
    }
    const float* M = (blockIdx.x == 0) ? W : (blockIdx.x == 1) ? Wr : Nw;
    unsigned char* img = g_Bimg[blockIdx.x];
    for (int idx = threadIdx.x; idx < 128 * 128; idx += 256) {
        int k = idx >> 7, n = idx & 127;
        float v = M[idx];
        __half h, l;
        h_split(v, h, l);
        uint32_t off = img_off(n, k);
        *reinterpret_cast<__half*>(img + off) = h;
        *reinterpret_cast<__half*>(img + 32768 + off) = l;
    }
}

// ================= shared GEMM mainloop (128x128 CTA tile, 512 thr) =================
// smem: A 32KB | BH 32KB | BL 32KB = 96KB -> 2 CTAs/SM, 32 warps/SM.
// Warp tile 16 rows x 64 cols: wr = wid>>1 (8 row bands), wc = wid&1.
// B fetched with ldmatrix.x4 covering TWO 8-col bands per issue.
struct GemmCore {
    int r0w, c0w;
    float acc[8][4];

    __device__ __forceinline__ void run(uint32_t sb, int wid, int lane) {
        const uint32_t AH = sb, BH = sb + 32768, BL = sb + 65536;
        r0w = (wid >> 1) * 16;
        c0w = (wid & 1) * 64;

        const int rA = lane & 15;
        const int uA = lane >> 4;
        const int axr = rA & 7;
        const int g = lane >> 3;       // 0..3
        const int rr = lane & 7;
        const int ubB = g & 1;
        const int nbo = g >> 1;

        const uint32_t arow = (uint32_t)(r0w + rA) * 256;
        uint32_t browp[4];
#pragma unroll
        for (int nbp = 0; nbp < 4; ++nbp)
            browp[nbp] = (uint32_t)(c0w + (2 * nbp + nbo) * 8 + rr) * 256;

#pragma unroll
        for (int nb = 0; nb < 8; ++nb) {
            acc[nb][0] = 0.f; acc[nb][1] = 0.f;
            acc[nb][2] = 0.f; acc[nb][3] = 0.f;
        }

#pragma unroll
        for (int kb = 0; kb < 8; ++kb) {
            uint32_t offA = (uint32_t)((2 * kb + uA) ^ axr) << 4;
            uint32_t offB = (uint32_t)((2 * kb + ubB) ^ rr) << 4;
            uint32_t ah[4];
            ldsm_x4(ah, AH + arow + offA);
#pragma unroll
            for (int nbp = 0; nbp < 4; ++nbp) {
                uint32_t bh[4], bl[4];
                ldsm_x4(bh, BH + browp[nbp] + offB);
                ldsm_x4(bl, BL + browp[nbp] + offB);
                mma_f16(acc[2 * nbp],     ah, bh[0], bh[1]);
                mma_f16(acc[2 * nbp],     ah, bl[0], bl[1]);
                mma_f16(acc[2 * nbp + 1], ah, bh[2], bh[3]);
                mma_f16(acc[2 * nbp + 1], ah, bl[2], bl[3]);
            }
        }
    }
};

// ---------------------------------------------------------------
// Fused h_node / h_rel GEMM (512 threads).  Blocks [0, NB): ent.
// Blocks [NB, NB+4): rel.  2-pass Ah*Bh + Ah*Bl.
// ---------------------------------------------------------------
__global__ void __launch_bounds__(512, 2) gemm_node_rel(const float* __restrict__ ent,
                                                        const float* __restrict__ rel,
                                                        const unsigned char* __restrict__ img) {
    extern __shared__ __align__(16) unsigned char dynsm[];

    const int tid = threadIdx.x;
    const int wid = tid >> 5;
    const int lane = tid & 31;
    const bool isNode = blockIdx.x < NB;
    const int row0 = (isNode ? blockIdx.x : blockIdx.x - NB) * 128;
    const int M = isNode ? NENT : NRELN;
    const float* A = isNode ? ent : rel;
    const unsigned char* Bimg = img + (isNode ? 0 : 65536);
    const uint32_t sb = smem_u32(dynsm);

    // ---- B: straight 64KB copy of pre-swizzled hi|lo image ----
    {
        const uint4* srcB = reinterpret_cast<const uint4*>(Bimg);
        uint4* dstB = reinterpret_cast<uint4*>(dynsm + 32768);
#pragma unroll
        for (int i = 0; i < 8; ++i) dstB[tid + i * 512] = srcB[tid + i * 512];
    }
    // ---- A: load fp32, convert fp16, swizzled store; fused exact scores ----
    {
        const int u = tid & 15;
        const int wi = isNode ? 0 : 2;
        float4 wa = *reinterpret_cast<const float4*>(&g_wv[wi][u * 8]);
        float4 wb = *reinterpret_cast<const float4*>(&g_wv[wi][u * 8 + 4]);
        float4 wc = *reinterpret_cast<const float4*>(&g_wv[1][u * 8]);
        float4 wd = *reinterpret_cast<const float4*>(&g_wv[1][u * 8 + 4]);
#pragma unroll
        for (int it = 0; it < 4; ++it) {
            int idx = tid + it * 512;
            int r = idx >> 4;
            int gr = row0 + r;
            float4 v0 = make_float4(0.f, 0.f, 0.f, 0.f);
            float4 v1 = v0;
            if (gr < M) {
                v0 = *reinterpret_cast<const float4*>(A + (size_t)gr * HD + u * 8);
                v1 = *reinterpret_cast<const float4*>(A + (size_t)gr * HD + u * 8 + 4);
            }
            uint32_t off = r * 256 + (((u ^ (r & 7))) << 4);
            *reinterpret_cast<uint4*>(dynsm + off) = make_uint4(
                pack2(__float2half_rn(v0.x), __float2half_rn(v0.y)),
                pack2(__float2half_rn(v0.z), __float2half_rn(v0.w)),
                pack2(__float2half_rn(v1.x), __float2half_rn(v1.y)),
                pack2(__float2half_rn(v1.z), __float2half_rn(v1.w)));
            float p1 = v0.x * wa.x + v0.y * wa.y + v0.z * wa.z + v0.w * wa.w +
                       v1.x * wb.x + v1.y * wb.y + v1.z * wb.z + v1.w * wb.w;
            float p2 = 0.f;
            if (isNode)
                p2 = v0.x * wc.x + v0.y * wc.y + v0.z * wc.z + v0.w * wc.w +
                     v1.x * wd.x + v1.y * wd.y + v1.z * wd.z + v1.w * wd.w;
#pragma unroll
            for (int o = 1; o < 16; o <<= 1) {
                p1 += __shfl_xor_sync(0xffffffffu, p1, o);
                p2 += __shfl_xor_sync(0xffffffffu, p2, o);
            }
            if ((tid & 15) == 0 && gr < M) {
                if (isNode) {
                    g_ssrc[gr] = p1;
                    g_sdst[gr] = p2;
                } else {
                    g_srel[gr] = p1;
                }
            }
        }
    }
    __syncthreads();

    GemmCore core;
    core.run(sb, wid, lane);

    // ---- epilogue: fp16 image ----
    const int tg = lane >> 2, tig = lane & 3;
    uint32_t* dstImg = isNode ? g_hnodeh : g_hrelh;
#pragma unroll
    for (int nb = 0; nb < 8; ++nb) {
        float* d = core.acc[nb];
        int c = core.c0w + nb * 8 + tig * 2;
        int r1 = row0 + core.r0w + tg;
        if (r1 < M)
            dstImg[(size_t)r1 * 64 + (c >> 1)] = pack2(__float2half_rn(d[0]), __float2half_rn(d[1]));
        if (r1 + 8 < M)
            dstImg[(size_t)(r1 + 8) * 64 + (c >> 1)] = pack2(__float2half_rn(d[2]), __float2half_rn(d[3]));
    }
}

// ---------------------------------------------------------------
// Final GEMM (512 threads): out = tanh(neighh @ neigh_w).  A fp16 exact.
// ---------------------------------------------------------------
__global__ void __launch_bounds__(512, 2) gemm_out(const uint32_t* __restrict__ neighh,
                                                   const unsigned char* __restrict__ Bimg,
                                                   float* __restrict__ C, int M) {
    extern __shared__ __align__(16) unsigned char dynsm[];

    const int tid = threadIdx.x;
    const int wid = tid >> 5;
    const int lane = tid & 31;
    const int row0 = blockIdx.x * 128;
    const uint32_t sb = smem_u32(dynsm);

    // B: straight 64KB copy
    {
        const uint4* srcB = reinterpret_cast<const uint4*>(Bimg);
        uint4* dstB = reinterpret_cast<uint4*>(dynsm + 32768);
#pragma unroll
        for (int i = 0; i < 8; ++i) dstB[tid + i * 512] = srcB[tid + i * 512];
    }
    // A: straight swizzled copy (fp16 image, exact)
    {
        const uint4* srcA = reinterpret_cast<const uint4*>(neighh) + (size_t)row0 * 16;
#pragma unroll
        for (int it = 0; it < 4; ++it) {
            int idx = tid + it * 512;
            int r = idx >> 4;
            int u = idx & 15;
            uint4 v = srcA[idx];
            *reinterpret_cast<uint4*>(dynsm + r * 256 + (((u ^ (r & 7))) << 4)) = v;
        }
    }
    __syncthreads();

    GemmCore core;
    core.run(sb, wid, lane);

    const int tg = lane >> 2, tig = lane & 3;
#pragma unroll
    for (int nb = 0; nb < 8; ++nb) {
        float* d = core.acc[nb];
        int c = core.c0w + nb * 8 + tig * 2;
        int r1 = row0 + core.r0w + tg;
        if (r1 < M)
            *reinterpret_cast<float2*>(C + (size_t)r1 * HD + c) =
                make_float2(tanhf(d[0]), tanhf(d[1]));
        if (r1 + 8 < M)
            *reinterpret_cast<float2*>(C + (size_t)(r1 + 8) * HD + c) =
                make_float2(tanhf(d[2]), tanhf(d[3]));
    }
}

// ---------------------------------------------------------------
// Attention: warp per node; rank-based top-k; rank = compaction slot.
// Gather: 16 lanes/neighbor, 2 neighbors/iter via LDG.128.
// ---------------------------------------------------------------
__global__ void __launch_bounds__(256) attn_kernel(const int* __restrict__ src,
                                                   const int* __restrict__ relid) {
    __shared__ __align__(16) float ssc[8][32];
    __shared__ float swgt[8][16];
    __shared__ int spk[8][16];

    int warp = (blockIdx.x * blockDim.x + threadIdx.x) >> 5;
    int w = threadIdx.x >> 5;
    int lane = threadIdx.x & 31;
    if (warp >= NENT) return;
    const int n = warp;

    int s_id = src[(size_t)n * DEG + lane];
    int r_id = relid[(size_t)n * DEG + lane];
    float sc = g_ssrc[s_id] + g_sdst[n] + g_srel[r_id];
    sc = sc > 0.f ? sc : 0.2f * sc;  // leaky_relu 0.2

    ssc[w][lane] = sc;
    __syncwarp();
    int rank = 0;
#pragma unroll
    for (int j4 = 0; j4 < 8; ++j4) {
        float4 q = *reinterpret_cast<const float4*>(&ssc[w][j4 * 4]);
        int j = j4 * 4;
        rank += (q.x > sc) || (q.x == sc && (j + 0) < lane);
        rank += (q.y > sc) || (q.y == sc && (j + 1) < lane);
        rank += (q.z > sc) || (q.z == sc && (j + 2) < lane);
        rank += (q.w > sc) || (q.w == sc && (j + 3) < lane);
    }
    bool sel = rank < TOPK;

    float p = sel ? __expf(sc) : 0.f;
    float s = p;
#pragma unroll
    for (int o = 16; o; o >>= 1) s += __shfl_xor_sync(0xffffffffu, s, o);

    if (sel) {
        swgt[w][rank] = p / s;
        spk[w][rank] = s_id | (r_id << 18);
    }
    __syncwarp();

    const int half = lane >> 4;
    const int j = lane & 15;
    float acc[8];
#pragma unroll
    for (int d = 0; d < 8; ++d) acc[d] = 0.f;

#pragma unroll
    for (int it = 0; it < 5; ++it) {
        int k = it * 2 + half;
        float wgt = swgt[w][k];
        int pks = spk[w][k];
        int sk = pks & 0x3FFFF;
        int rk = pks >> 18;
        uint4 hn = *reinterpret_cast<const uint4*>(g_hnodeh + (size_t)sk * 64 + j * 4);
        uint4 hr = *reinterpret_cast<const uint4*>(g_hrelh + rk * 64 + j * 4);
        float2 f0 = __half22float2(__hadd2(u2h2(hn.x), u2h2(hr.x)));
        float2 f1 = __half22float2(__hadd2(u2h2(hn.y), u2h2(hr.y)));
        float2 f2 = __half22float2(__hadd2(u2h2(hn.z), u2h2(hr.z)));
        float2 f3 = __half22float2(__hadd2(u2h2(hn.w), u2h2(hr.w)));
        acc[0] += wgt * f0.x; acc[1] += wgt * f0.y;
        acc[2] += wgt * f1.x; acc[3] += wgt * f1.y;
        acc[4] += wgt * f2.x; acc[5] += wgt * f2.y;
        acc[6] += wgt * f3.x; acc[7] += wgt * f3.y;
    }

#pragma unroll
    for (int d = 0; d < 8; ++d) acc[d] += __shfl_down_sync(0xffffffffu, acc[d], 16);

    if (lane < 16) {
        uint4 o;
        o.x = pack2(__float2half_rn(acc[0]), __float2half_rn(acc[1]));
        o.y = pack2(__float2half_rn(acc[2]), __float2half_rn(acc[3]));
        o.z = pack2(__float2half_rn(acc[4]), __float2half_rn(acc[5]));
        o.w = pack2(__float2half_rn(acc[6]), __float2half_rn(acc[7]));
        *reinterpret_cast<uint4*>(g_neighh + (size_t)n * 64 + j * 4) = o;
    }
}

// ---------------------------------------------------------------
extern "C" void kernel_launch(void* const* d_in, const int* in_sizes, int n_in,
                              void* d_out, int out_size) {
    const float* ent   = (const float*)d_in[0];
    const float* rel   = (const float*)d_in[1];
    const float* W     = (const float*)d_in[2];
    const float* Wr    = (const float*)d_in[3];
    const float* a     = (const float*)d_in[4];
    const float* nw    = (const float*)d_in[5];
    const int*   src   = (const int*)d_in[6];
    const int*   relid = (const int*)d_in[7];
    float* out = (float*)d_out;

    uint32_t* p_neighh;
    unsigned char* p_img;
    cudaGetSymbolAddress((void**)&p_neighh, g_neighh);
    cudaGetSymbolAddress((void**)&p_img, g_Bimg);

    const int SMEM = 98304;
    cudaFuncSetAttribute(gemm_node_rel, cudaFuncAttributeMaxDynamicSharedMemorySize, SMEM);
    cudaFuncSetAttribute(gemm_out, cudaFuncAttributeMaxDynamicSharedMemorySize, SMEM);

    prep_kernel<<<4, 256>>>(W, Wr, nw, a);

    // h_node + h_rel (fp16 images) + exact fp32 scores, fused (512 thr)
    gemm_node_rel<<<NB + 4, 512, SMEM>>>(ent, rel, p_img);
    // attention + aggregation (fp16 gathers, fp16 neigh out)
    attn_kernel<<<(NENT * 32 + 255) / 256, 256>>>(src, relid);
    // out = tanh(neigh @ neigh_w) (512 thr)
    gemm_out<<<NB, 512, SMEM>>>(p_neighh, p_img + 2 * 65536, out, NENT);
}

// round 16
// speedup vs baseline: 1.0911x; 1.0911x over previous
#include <cuda_runtime.h>
#include <cuda_fp16.h>
#include <math.h>
#include <stdint.h>

#define NENT 150000
#define NRELN 500
#define HD 128
#define DEG 32
#define TOPK 10
#define NB 1172   // ceil(NENT/128)

// -------- scratch (device globals; no allocation allowed) --------
__device__ uint32_t g_neighh[150016 * 64];  // neigh as half2 pairs
__device__ uint32_t g_hnodeh[150016 * 64];  // h_node as half2 pairs
__device__ uint32_t g_hrelh[512 * 64];      // h_rel  as half2 pairs
__device__ float g_ssrc[150016];
__device__ float g_sdst[150016];
__device__ float g_srel[512];
__device__ float g_wv[3][128];              // W@a1, W@a2, Wr@a3 (exact score vectors)
// pre-transposed + swizzled fp16-split weight images: [matrix][hi 32KB | lo 32KB]
__device__ __align__(16) unsigned char g_Bimg[3][65536];

// ================= helpers =================
__device__ __forceinline__ uint32_t smem_u32(const void* p) {
    uint32_t a;
    asm("{ .reg .u64 t; cvta.to.shared.u64 t, %1; cvt.u32.u64 %0, t; }" : "=r"(a) : "l"(p));
    return a;
}
__device__ __forceinline__ void ldsm_x4(uint32_t* r, uint32_t addr) {
    asm volatile("ldmatrix.sync.aligned.m8n8.x4.shared.b16 {%0,%1,%2,%3}, [%4];"
                 : "=r"(r[0]), "=r"(r[1]), "=r"(r[2]), "=r"(r[3]) : "r"(addr));
}
__device__ __forceinline__ void mma_f16(float* d, const uint32_t* a, uint32_t b0, uint32_t b1) {
    asm volatile(
        "mma.sync.aligned.m16n8k16.row.col.f32.f16.f16.f32 "
        "{%0,%1,%2,%3}, {%4,%5,%6,%7}, {%8,%9}, {%0,%1,%2,%3};"
        : "+f"(d[0]), "+f"(d[1]), "+f"(d[2]), "+f"(d[3])
        : "r"(a[0]), "r"(a[1]), "r"(a[2]), "r"(a[3]), "r"(b0), "r"(b1));
}
__device__ __forceinline__ void h_split(float v, __half& h, __half& l) {
    h = __float2half_rn(v);
    l = __float2half_rn(v - __half2float(h));
}
__device__ __forceinline__ uint32_t pack2(__half a, __half b) {
    __half2 t;
    t.x = a; t.y = b;
    return *reinterpret_cast<uint32_t*>(&t);
}
__device__ __forceinline__ __half2 u2h2(uint32_t u) {
    return *reinterpret_cast<__half2*>(&u);
}
// tile layout: row-major rows of 128 f16 (256B = 16 units of 16B), unit XOR-swizzled
__device__ __forceinline__ uint32_t img_off(int n, int k) {
    return (uint32_t)(n * 256 + ((((k >> 3) ^ (n & 7))) << 4) + (k & 7) * 2);
}

// ---------------------------------------------------------------
// prep: blockIdx 0..2 build weight images; blockIdx 3 computes the
// exact score vectors w1 = W@a1, w2 = W@a2, w3 = Wr@a3 (fp32).
// ---------------------------------------------------------------
__global__ void __launch_bounds__(256) prep_kernel(const float* __restrict__ W,
                                                   const float* __restrict__ Wr,
                                                   const float* __restrict__ Nw,
                                                   const float* __restrict__ a) {
    if (blockIdx.x == 3) {
        int k = threadIdx.x;
        if (k < 128) {
            float d1 = 0.f, d2 = 0.f;
            for (int n = 0; n < 128; ++n) {
                float wv = W[k * 128 + n];
                d1 += wv * a[n];
                d2 += wv * a[128 + n];
            }
            g_wv[0][k] = d1;
            g_wv[1][k] = d2;
        } else {
            int kk = k - 128;
            float d3 = 0.f;
            for (int n = 0; n < 128; ++n) d3 += Wr[kk * 128 + n] * a[256 + n];
            g_wv[2][kk] = d3;
        }
        return;
    }
    const float* M = (blockIdx.x == 0) ? W : (blockIdx.x == 1) ? Wr : Nw;
    unsigned char* img = g_Bimg[blockIdx.x];
    for (int idx = threadIdx.x; idx < 128 * 128; idx += 256) {
        int k = idx >> 7, n = idx & 127;
        float v = M[idx];
        __half h, l;
        h_split(v, h, l);
        uint32_t off = img_off(n, k);
        *reinterpret_cast<__half*>(img + off) = h;
        *reinterpret_cast<__half*>(img + 32768 + off) = l;
    }
}

// ================= shared GEMM mainloop (128x128 CTA tile, 256 thr) =================
// Warp tile 32 rows x 64 cols.  B fetched with ldmatrix.x4 covering TWO 8-col
// bands per issue (lane group g supplies (band pair, k-half)).
// NPASS=2: A*Bh + A*Bl (BL at sb+64KB).  NPASS=1: A*Bh only.
template <int NPASS>
struct GemmCore {
    int r0w, c0w;
    float acc[2][8][4];

    __device__ __forceinline__ void run(uint32_t sb, int wid, int lane) {
        const uint32_t AH = sb, BH = sb + 32768, BL = sb + 65536;
        r0w = (wid >> 1) * 32;
        c0w = (wid & 1) * 64;

        const int rA = lane & 15;
        const int uA = lane >> 4;
        const int axr = rA & 7;
        const int g = lane >> 3;       // 0..3
        const int rr = lane & 7;
        const int ubB = g & 1;
        const int nbo = g >> 1;

        uint32_t arow[2], browp[4];
#pragma unroll
        for (int rb = 0; rb < 2; ++rb) arow[rb] = (uint32_t)(r0w + rb * 16 + rA) * 256;
#pragma unroll
        for (int nbp = 0; nbp < 4; ++nbp)
            browp[nbp] = (uint32_t)(c0w + (2 * nbp + nbo) * 8 + rr) * 256;

#pragma unroll
        for (int rb = 0; rb < 2; ++rb)
#pragma unroll
            for (int nb = 0; nb < 8; ++nb) {
                acc[rb][nb][0] = 0.f; acc[rb][nb][1] = 0.f;
                acc[rb][nb][2] = 0.f; acc[rb][nb][3] = 0.f;
            }

#pragma unroll
        for (int kb = 0; kb < 8; ++kb) {
            uint32_t offA = (uint32_t)((2 * kb + uA) ^ axr) << 4;
            uint32_t offB = (uint32_t)((2 * kb + ubB) ^ rr) << 4;
            uint32_t ah[2][4];
            ldsm_x4(ah[0], AH + arow[0] + offA);
            ldsm_x4(ah[1], AH + arow[1] + offA);
#pragma unroll
            for (int nbp = 0; nbp < 4; ++nbp) {
                uint32_t bh[4];
                ldsm_x4(bh, BH + browp[nbp] + offB);
                if (NPASS == 2) {
                    uint32_t bl[4];
                    ldsm_x4(bl, BL + browp[nbp] + offB);
#pragma unroll
                    for (int rb = 0; rb < 2; ++rb) {
                        mma_f16(acc[rb][2 * nbp],     ah[rb], bh[0], bh[1]);
                        mma_f16(acc[rb][2 * nbp],     ah[rb], bl[0], bl[1]);
                        mma_f16(acc[rb][2 * nbp + 1], ah[rb], bh[2], bh[3]);
                        mma_f16(acc[rb][2 * nbp + 1], ah[rb], bl[2], bl[3]);
                    }
                } else {
#pragma unroll
                    for (int rb = 0; rb < 2; ++rb) {
                        mma_f16(acc[rb][2 * nbp],     ah[rb], bh[0], bh[1]);
                        mma_f16(acc[rb][2 * nbp + 1], ah[rb], bh[2], bh[3]);
                    }
                }
            }
        }
    }
};

// ---------------------------------------------------------------
// Fused h_node / h_rel GEMM.  Blocks [0, NB): ent -> g_hnodeh + s_src/s_dst.
// Blocks [NB, NB+4): rel -> g_hrelh + s_rel.  2-pass Ah*Bh + Ah*Bl (96KB smem).
// ---------------------------------------------------------------
__global__ void __launch_bounds__(256) gemm_node_rel(const float* __restrict__ ent,
                                                     const float* __restrict__ rel,
                                                     const unsigned char* __restrict__ img) {
    extern __shared__ __align__(16) unsigned char dynsm[];

    const int tid = threadIdx.x;
    const int wid = tid >> 5;
    const int lane = tid & 31;
    const bool isNode = blockIdx.x < NB;
    const int row0 = (isNode ? blockIdx.x : blockIdx.x - NB) * 128;
    const int M = isNode ? NENT : NRELN;
    const float* A = isNode ? ent : rel;
    const unsigned char* Bimg = img + (isNode ? 0 : 65536);
    const uint32_t sb = smem_u32(dynsm);

    // ---- B: straight 64KB copy of pre-swizzled hi|lo image ----
    {
        const uint4* srcB = reinterpret_cast<const uint4*>(Bimg);
        uint4* dstB = reinterpret_cast<uint4*>(dynsm + 32768);
#pragma unroll
        for (int i = 0; i < 16; ++i) dstB[tid + i * 256] = srcB[tid + i * 256];
    }
    // ---- A: load fp32, convert fp16, swizzled store; fused exact scores ----
    {
        const int u = tid & 15;
        const int wi = isNode ? 0 : 2;
        float4 wa = *reinterpret_cast<const float4*>(&g_wv[wi][u * 8]);
        float4 wb = *reinterpret_cast<const float4*>(&g_wv[wi][u * 8 + 4]);
        float4 wc = *reinterpret_cast<const float4*>(&g_wv[1][u * 8]);
        float4 wd = *reinterpret_cast<const float4*>(&g_wv[1][u * 8 + 4]);
#pragma unroll
        for (int it = 0; it < 8; ++it) {
            int idx = tid + it * 256;
            int r = idx >> 4;
            int gr = row0 + r;
            float4 v0 = make_float4(0.f, 0.f, 0.f, 0.f);
            float4 v1 = v0;
            if (gr < M) {
                v0 = *reinterpret_cast<const float4*>(A + (size_t)gr * HD + u * 8);
                v1 = *reinterpret_cast<const float4*>(A + (size_t)gr * HD + u * 8 + 4);
            }
            uint32_t off = r * 256 + (((u ^ (r & 7))) << 4);
            *reinterpret_cast<uint4*>(dynsm + off) = make_uint4(
                pack2(__float2half_rn(v0.x), __float2half_rn(v0.y)),
                pack2(__float2half_rn(v0.z), __float2half_rn(v0.w)),
                pack2(__float2half_rn(v1.x), __float2half_rn(v1.y)),
                pack2(__float2half_rn(v1.z), __float2half_rn(v1.w)));
            float p1 = v0.x * wa.x + v0.y * wa.y + v0.z * wa.z + v0.w * wa.w +
                       v1.x * wb.x + v1.y * wb.y + v1.z * wb.z + v1.w * wb.w;
            float p2 = 0.f;
            if (isNode)
                p2 = v0.x * wc.x + v0.y * wc.y + v0.z * wc.z + v0.w * wc.w +
                     v1.x * wd.x + v1.y * wd.y + v1.z * wd.z + v1.w * wd.w;
#pragma unroll
            for (int o = 1; o < 16; o <<= 1) {
                p1 += __shfl_xor_sync(0xffffffffu, p1, o);
                p2 += __shfl_xor_sync(0xffffffffu, p2, o);
            }
            if ((tid & 15) == 0 && gr < M) {
                if (isNode) {
                    g_ssrc[gr] = p1;
                    g_sdst[gr] = p2;
                } else {
                    g_srel[gr] = p1;
                }
            }
        }
    }
    __syncthreads();

    GemmCore<2> core;
    core.run(sb, wid, lane);

    // ---- epilogue: fp16 image ----
    const int tg = lane >> 2, tig = lane & 3;
    uint32_t* dstImg = isNode ? g_hnodeh : g_hrelh;
#pragma unroll
    for (int rb = 0; rb < 2; ++rb)
#pragma unroll
        for (int nb = 0; nb < 8; ++nb) {
            float* d = core.acc[rb][nb];
            int c = core.c0w + nb * 8 + tig * 2;
            int r1 = row0 + core.r0w + rb * 16 + tg;
            if (r1 < M)
                dstImg[(size_t)r1 * 64 + (c >> 1)] = pack2(__float2half_rn(d[0]), __float2half_rn(d[1]));
            if (r1 + 8 < M)
                dstImg[(size_t)(r1 + 8) * 64 + (c >> 1)] = pack2(__float2half_rn(d[2]), __float2half_rn(d[3]));
        }
}

// ---------------------------------------------------------------
// Final GEMM: out = tanh(neighh @ neigh_w).  Single-pass A*Bh
// (A already fp16-rounded; B-lo term ~2^-12 relative — dropped).
// smem: A 32KB | BH 32KB = 64KB -> 3 CTAs/SM.
// ---------------------------------------------------------------
__global__ void __launch_bounds__(256) gemm_out(const uint32_t* __restrict__ neighh,
                                                const unsigned char* __restrict__ Bimg,
                                                float* __restrict__ C, int M) {
    extern __shared__ __align__(16) unsigned char dynsm[];

    const int tid = threadIdx.x;
    const int wid = tid >> 5;
    const int lane = tid & 31;
    const int row0 = blockIdx.x * 128;
    const uint32_t sb = smem_u32(dynsm);

    // BH only: 32KB copy
    {
        const uint4* srcB = reinterpret_cast<const uint4*>(Bimg);
        uint4* dstB = reinterpret_cast<uint4*>(dynsm + 32768);
#pragma unroll
        for (int i = 0; i < 8; ++i) dstB[tid + i * 256] = srcB[tid + i * 256];
    }
    // A: straight swizzled copy (fp16 image, exact)
    {
        const uint4* srcA = reinterpret_cast<const uint4*>(neighh) + (size_t)row0 * 16;
#pragma unroll
        for (int it = 0; it < 8; ++it) {
            int idx = tid + it * 256;
            int r = idx >> 4;
            int u = idx & 15;
            uint4 v = srcA[idx];
            *reinterpret_cast<uint4*>(dynsm + r * 256 + (((u ^ (r & 7))) << 4)) = v;
        }
    }
    __syncthreads();

    GemmCore<1> core;
    core.run(sb, wid, lane);

    const int tg = lane >> 2, tig = lane & 3;
#pragma unroll
    for (int rb = 0; rb < 2; ++rb)
#pragma unroll
        for (int nb = 0; nb < 8; ++nb) {
            float* d = core.acc[rb][nb];
            int c = core.c0w + nb * 8 + tig * 2;
            int r1 = row0 + core.r0w + rb * 16 + tg;
            if (r1 < M)
                *reinterpret_cast<float2*>(C + (size_t)r1 * HD + c) =
                    make_float2(tanhf(d[0]), tanhf(d[1]));
            if (r1 + 8 < M)
                *reinterpret_cast<float2*>(C + (size_t)(r1 + 8) * HD + c) =
                    make_float2(tanhf(d[2]), tanhf(d[3]));
        }
}

// ---------------------------------------------------------------
// Attention: warp per node; rank-based top-k; rank = compaction slot.
// Gather: 16 lanes/neighbor, 2 neighbors/iter via LDG.128.
// ---------------------------------------------------------------
__global__ void __launch_bounds__(256) attn_kernel(const int* __restrict__ src,
                                                   const int* __restrict__ relid) {
    __shared__ __align__(16) float ssc[8][32];
    __shared__ float swgt[8][16];
    __shared__ int spk[8][16];

    int warp = (blockIdx.x * blockDim.x + threadIdx.x) >> 5;
    int w = threadIdx.x >> 5;
    int lane = threadIdx.x & 31;
    if (warp >= NENT) return;
    const int n = warp;

    int s_id = src[(size_t)n * DEG + lane];
    int r_id = relid[(size_t)n * DEG + lane];
    float sc = g_ssrc[s_id] + g_sdst[n] + g_srel[r_id];
    sc = sc > 0.f ? sc : 0.2f * sc;  // leaky_relu 0.2

    ssc[w][lane] = sc;
    __syncwarp();
    int rank = 0;
#pragma unroll
    for (int j4 = 0; j4 < 8; ++j4) {
        float4 q = *reinterpret_cast<const float4*>(&ssc[w][j4 * 4]);
        int j = j4 * 4;
        rank += (q.x > sc) || (q.x == sc && (j + 0) < lane);
        rank += (q.y > sc) || (q.y == sc && (j + 1) < lane);
        rank += (q.z > sc) || (q.z == sc && (j + 2) < lane);
        rank += (q.w > sc) || (q.w == sc && (j + 3) < lane);
    }
    bool sel = rank < TOPK;

    float p = sel ? __expf(sc) : 0.f;
    float s = p;
#pragma unroll
    for (int o = 16; o; o >>= 1) s += __shfl_xor_sync(0xffffffffu, s, o);

    if (sel) {
        swgt[w][rank] = p / s;
        spk[w][rank] = s_id | (r_id << 18);
    }
    __syncwarp();

    const int half = lane >> 4;
    const int j = lane & 15;
    float acc[8];
#pragma unroll
    for (int d = 0; d < 8; ++d) acc[d] = 0.f;

#pragma unroll
    for (int it = 0; it < 5; ++it) {
        int k = it * 2 + half;
        float wgt = swgt[w][k];
        int pks = spk[w][k];
        int sk = pks & 0x3FFFF;
        int rk = pks >> 18;
        uint4 hn = *reinterpret_cast<const uint4*>(g_hnodeh + (size_t)sk * 64 + j * 4);
        uint4 hr = *reinterpret_cast<const uint4*>(g_hrelh + rk * 64 + j * 4);
        float2 f0 = __half22float2(__hadd2(u2h2(hn.x), u2h2(hr.x)));
        float2 f1 = __half22float2(__hadd2(u2h2(hn.y), u2h2(hr.y)));
        float2 f2 = __half22float2(__hadd2(u2h2(hn.z), u2h2(hr.z)));
        float2 f3 = __half22float2(__hadd2(u2h2(hn.w), u2h2(hr.w)));
        acc[0] += wgt * f0.x; acc[1] += wgt * f0.y;
        acc[2] += wgt * f1.x; acc[3] += wgt * f1.y;
        acc[4] += wgt * f2.x; acc[5] += wgt * f2.y;
        acc[6] += wgt * f3.x; acc[7] += wgt * f3.y;
    }

#pragma unroll
    for (int d = 0; d < 8; ++d) acc[d] += __shfl_down_sync(0xffffffffu, acc[d], 16);

    if (lane < 16) {
        uint4 o;
        o.x = pack2(__float2half_rn(acc[0]), __float2half_rn(acc[1]));
        o.y = pack2(__float2half_rn(acc[2]), __float2half_rn(acc[3]));
        o.z = pack2(__float2half_rn(acc[4]), __float2half_rn(acc[5]));
        o.w = pack2(__float2half_rn(acc[6]), __float2half_rn(acc[7]));
        *reinterpret_cast<uint4*>(g_neighh + (size_t)n * 64 + j * 4) = o;
    }
}

// ---------------------------------------------------------------
extern "C" void kernel_launch(void* const* d_in, const int* in_sizes, int n_in,
                              void* d_out, int out_size) {
    const float* ent   = (const float*)d_in[0];
    const float* rel   = (const float*)d_in[1];
    const float* W     = (const float*)d_in[2];
    const float* Wr    = (const float*)d_in[3];
    const float* a     = (const float*)d_in[4];
    const float* nw    = (const float*)d_in[5];
    const int*   src   = (const int*)d_in[6];
    const int*   relid = (const int*)d_in[7];
    float* out = (float*)d_out;

    uint32_t* p_neighh;
    unsigned char* p_img;
    cudaGetSymbolAddress((void**)&p_neighh, g_neighh);
    cudaGetSymbolAddress((void**)&p_img, g_Bimg);

    cudaFuncSetAttribute(gemm_node_rel, cudaFuncAttributeMaxDynamicSharedMemorySize, 98304);
    cudaFuncSetAttribute(gemm_out, cudaFuncAttributeMaxDynamicSharedMemorySize, 65536);

    prep_kernel<<<4, 256>>>(W, Wr, nw, a);

    // h_node + h_rel (fp16 images) + exact fp32 scores, fused (2-pass)
    gemm_node_rel<<<NB + 4, 256, 98304>>>(ent, rel, p_img);
    // attention + aggregation (fp16 gathers, fp16 neigh out)
    attn_kernel<<<(NENT * 32 + 255) / 256, 256>>>(src, relid);
    // out = tanh(neigh @ neigh_w)  (single-pass, 64KB smem, 3 CTA/SM)
    gemm_out<<<NB, 256, 65536>>>(p_neighh, p_img + 2 * 65536, out, NENT);
}

// round 17
// speedup vs baseline: 1.2670x; 1.1611x over previous
#include <cuda_runtime.h>
#include <cuda_fp16.h>
#include <math.h>
#include <stdint.h>

#define NENT 150000
#define NRELN 500
#define HD 128
#define DEG 32
#define TOPK 10
#define NB 1172   // ceil(NENT/128)

// -------- scratch (device globals; no allocation allowed) --------
__device__ uint32_t g_neighh[150016 * 64];  // neigh as half2 pairs
__device__ uint32_t g_hnodeh[150016 * 64];  // h_node as half2 pairs
__device__ uint32_t g_hrelh[512 * 64];      // h_rel  as half2 pairs
__device__ float g_ssrc[150016];
__device__ float g_sdst[150016];
__device__ float g_srel[512];
__device__ float g_wv[3][128];              // W@a1, W@a2, Wr@a3 (exact score vectors)
// pre-transposed + swizzled fp16 weight images (hi words): [matrix][32KB]
// layout preserved from split version: matrix m at m*65536 (lo half unused)
__device__ __align__(16) unsigned char g_Bimg[3][65536];

// ================= helpers =================
__device__ __forceinline__ uint32_t smem_u32(const void* p) {
    uint32_t a;
    asm("{ .reg .u64 t; cvta.to.shared.u64 t, %1; cvt.u32.u64 %0, t; }" : "=r"(a) : "l"(p));
    return a;
}
__device__ __forceinline__ void ldsm_x4(uint32_t* r, uint32_t addr) {
    asm volatile("ldmatrix.sync.aligned.m8n8.x4.shared.b16 {%0,%1,%2,%3}, [%4];"
                 : "=r"(r[0]), "=r"(r[1]), "=r"(r[2]), "=r"(r[3]) : "r"(addr));
}
__device__ __forceinline__ void mma_f16(float* d, const uint32_t* a, uint32_t b0, uint32_t b1) {
    asm volatile(
        "mma.sync.aligned.m16n8k16.row.col.f32.f16.f16.f32 "
        "{%0,%1,%2,%3}, {%4,%5,%6,%7}, {%8,%9}, {%0,%1,%2,%3};"
        : "+f"(d[0]), "+f"(d[1]), "+f"(d[2]), "+f"(d[3])
        : "r"(a[0]), "r"(a[1]), "r"(a[2]), "r"(a[3]), "r"(b0), "r"(b1));
}
__device__ __forceinline__ uint32_t pack2(__half a, __half b) {
    __half2 t;
    t.x = a; t.y = b;
    return *reinterpret_cast<uint32_t*>(&t);
}
__device__ __forceinline__ __half2 u2h2(uint32_t u) {
    return *reinterpret_cast<__half2*>(&u);
}
// tile layout: row-major rows of 128 f16 (256B = 16 units of 16B), unit XOR-swizzled
__device__ __forceinline__ uint32_t img_off(int n, int k) {
    return (uint32_t)(n * 256 + ((((k >> 3) ^ (n & 7))) << 4) + (k & 7) * 2);
}

// ---------------------------------------------------------------
// prep: blockIdx 0..2 build fp16 weight images (hi only); blockIdx 3
// computes exact score vectors w1 = W@a1, w2 = W@a2, w3 = Wr@a3 (fp32).
// ---------------------------------------------------------------
__global__ void __launch_bounds__(256) prep_kernel(const float* __restrict__ W,
                                                   const float* __restrict__ Wr,
                                                   const float* __restrict__ Nw,
                                                   const float* __restrict__ a) {
    if (blockIdx.x == 3) {
        int k = threadIdx.x;
        if (k < 128) {
            float d1 = 0.f, d2 = 0.f;
            for (int n = 0; n < 128; ++n) {
                float wv = W[k * 128 + n];
                d1 += wv * a[n];
                d2 += wv * a[128 + n];
            }
            g_wv[0][k] = d1;
            g_wv[1][k] = d2;
        } else {
            int kk = k - 128;
            float d3 = 0.f;
            for (int n = 0; n < 128; ++n) d3 += Wr[kk * 128 + n] * a[256 + n];
            g_wv[2][kk] = d3;
        }
        return;
    }
    const float* M = (blockIdx.x == 0) ? W : (blockIdx.x == 1) ? Wr : Nw;
    unsigned char* img = g_Bimg[blockIdx.x];
    for (int idx = threadIdx.x; idx < 128 * 128; idx += 256) {
        int k = idx >> 7, n = idx & 127;
        *reinterpret_cast<__half*>(img + img_off(n, k)) = __float2half_rn(M[idx]);
    }
}

// ================= shared GEMM mainloop (128x128 CTA tile, 256 thr) =================
// Warp tile 32 rows x 64 cols.  Single pass A*Bh.  smem: A 32KB | BH 32KB.
// B fetched with ldmatrix.x4 covering TWO 8-col bands per issue.
struct GemmCore {
    int r0w, c0w;
    float acc[2][8][4];

    __device__ __forceinline__ void run(uint32_t sb, int wid, int lane) {
        const uint32_t AH = sb, BH = sb + 32768;
        r0w = (wid >> 1) * 32;
        c0w = (wid & 1) * 64;

        const int rA = lane & 15;
        const int uA = lane >> 4;
        const int axr = rA & 7;
        const int g = lane >> 3;       // 0..3
        const int rr = lane & 7;
        const int ubB = g & 1;
        const int nbo = g >> 1;

        uint32_t arow[2], browp[4];
#pragma unroll
        for (int rb = 0; rb < 2; ++rb) arow[rb] = (uint32_t)(r0w + rb * 16 + rA) * 256;
#pragma unroll
        for (int nbp = 0; nbp < 4; ++nbp)
            browp[nbp] = (uint32_t)(c0w + (2 * nbp + nbo) * 8 + rr) * 256;

#pragma unroll
        for (int rb = 0; rb < 2; ++rb)
#pragma unroll
            for (int nb = 0; nb < 8; ++nb) {
                acc[rb][nb][0] = 0.f; acc[rb][nb][1] = 0.f;
                acc[rb][nb][2] = 0.f; acc[rb][nb][3] = 0.f;
            }

#pragma unroll
        for (int kb = 0; kb < 8; ++kb) {
            uint32_t offA = (uint32_t)((2 * kb + uA) ^ axr) << 4;
            uint32_t offB = (uint32_t)((2 * kb + ubB) ^ rr) << 4;
            uint32_t ah[2][4];
            ldsm_x4(ah[0], AH + arow[0] + offA);
            ldsm_x4(ah[1], AH + arow[1] + offA);
#pragma unroll
            for (int nbp = 0; nbp < 4; ++nbp) {
                uint32_t bh[4];
                ldsm_x4(bh, BH + browp[nbp] + offB);
#pragma unroll
                for (int rb = 0; rb < 2; ++rb) {
                    mma_f16(acc[rb][2 * nbp],     ah[rb], bh[0], bh[1]);
                    mma_f16(acc[rb][2 * nbp + 1], ah[rb], bh[2], bh[3]);
                }
            }
        }
    }
};

// ---------------------------------------------------------------
// Fused h_node / h_rel GEMM.  Blocks [0, NB): ent -> g_hnodeh + s_src/s_dst.
// Blocks [NB, NB+4): rel -> g_hrelh + s_rel.  Single-pass A*Bh (64KB smem).
// Scores are EXACT fp32 (from fp32 A, precomputed w vectors) -> top-k exact.
// ---------------------------------------------------------------
__global__ void __launch_bounds__(256) gemm_node_rel(const float* __restrict__ ent,
                                                     const float* __restrict__ rel,
                                                     const unsigned char* __restrict__ img) {
    extern __shared__ __align__(16) unsigned char dynsm[];

    const int tid = threadIdx.x;
    const int wid = tid >> 5;
    const int lane = tid & 31;
    const bool isNode = blockIdx.x < NB;
    const int row0 = (isNode ? blockIdx.x : blockIdx.x - NB) * 128;
    const int M = isNode ? NENT : NRELN;
    const float* A = isNode ? ent : rel;
    const unsigned char* Bimg = img + (isNode ? 0 : 65536);
    const uint32_t sb = smem_u32(dynsm);

    // ---- B: 32KB copy of pre-swizzled hi image ----
    {
        const uint4* srcB = reinterpret_cast<const uint4*>(Bimg);
        uint4* dstB = reinterpret_cast<uint4*>(dynsm + 32768);
#pragma unroll
        for (int i = 0; i < 8; ++i) dstB[tid + i * 256] = srcB[tid + i * 256];
    }
    // ---- A: load fp32, convert fp16, swizzled store; fused exact scores ----
    {
        const int u = tid & 15;
        const int wi = isNode ? 0 : 2;
        float4 wa = *reinterpret_cast<const float4*>(&g_wv[wi][u * 8]);
        float4 wb = *reinterpret_cast<const float4*>(&g_wv[wi][u * 8 + 4]);
        float4 wc = *reinterpret_cast<const float4*>(&g_wv[1][u * 8]);
        float4 wd = *reinterpret_cast<const float4*>(&g_wv[1][u * 8 + 4]);
#pragma unroll
        for (int it = 0; it < 8; ++it) {
            int idx = tid + it * 256;
            int r = idx >> 4;
            int gr = row0 + r;
            float4 v0 = make_float4(0.f, 0.f, 0.f, 0.f);
            float4 v1 = v0;
            if (gr < M) {
                v0 = *reinterpret_cast<const float4*>(A + (size_t)gr * HD + u * 8);
                v1 = *reinterpret_cast<const float4*>(A + (size_t)gr * HD + u * 8 + 4);
            }
            uint32_t off = r * 256 + (((u ^ (r & 7))) << 4);
            *reinterpret_cast<uint4*>(dynsm + off) = make_uint4(
                pack2(__float2half_rn(v0.x), __float2half_rn(v0.y)),
                pack2(__float2half_rn(v0.z), __float2half_rn(v0.w)),
                pack2(__float2half_rn(v1.x), __float2half_rn(v1.y)),
                pack2(__float2half_rn(v1.z), __float2half_rn(v1.w)));
            float p1 = v0.x * wa.x + v0.y * wa.y + v0.z * wa.z + v0.w * wa.w +
                       v1.x * wb.x + v1.y * wb.y + v1.z * wb.z + v1.w * wb.w;
            float p2 = 0.f;
            if (isNode)
                p2 = v0.x * wc.x + v0.y * wc.y + v0.z * wc.z + v0.w * wc.w +
                     v1.x * wd.x + v1.y * wd.y + v1.z * wd.z + v1.w * wd.w;
#pragma unroll
            for (int o = 1; o < 16; o <<= 1) {
                p1 += __shfl_xor_sync(0xffffffffu, p1, o);
                p2 += __shfl_xor_sync(0xffffffffu, p2, o);
            }
            if ((tid & 15) == 0 && gr < M) {
                if (isNode) {
                    g_ssrc[gr] = p1;
                    g_sdst[gr] = p2;
                } else {
                    g_srel[gr] = p1;
                }
            }
        }
    }
    __syncthreads();

    GemmCore core;
    core.run(sb, wid, lane);

    // ---- epilogue: fp16 image ----
    const int tg = lane >> 2, tig = lane & 3;
    uint32_t* dstImg = isNode ? g_hnodeh : g_hrelh;
#pragma unroll
    for (int rb = 0; rb < 2; ++rb)
#pragma unroll
        for (int nb = 0; nb < 8; ++nb) {
            float* d = core.acc[rb][nb];
            int c = core.c0w + nb * 8 + tig * 2;
            int r1 = row0 + core.r0w + rb * 16 + tg;
            if (r1 < M)
                dstImg[(size_t)r1 * 64 + (c >> 1)] = pack2(__float2half_rn(d[0]), __float2half_rn(d[1]));
            if (r1 + 8 < M)
                dstImg[(size_t)(r1 + 8) * 64 + (c >> 1)] = pack2(__float2half_rn(d[2]), __float2half_rn(d[3]));
        }
}

// ---------------------------------------------------------------
// Final GEMM: out = tanh(neighh @ neigh_w).  Single-pass A*Bh, 64KB smem.
// ---------------------------------------------------------------
__global__ void __launch_bounds__(256) gemm_out(const uint32_t* __restrict__ neighh,
                                                const unsigned char* __restrict__ Bimg,
                                                float* __restrict__ C, int M) {
    extern __shared__ __align__(16) unsigned char dynsm[];

    const int tid = threadIdx.x;
    const int wid = tid >> 5;
    const int lane = tid & 31;
    const int row0 = blockIdx.x * 128;
    const uint32_t sb = smem_u32(dynsm);

    // BH: 32KB copy
    {
        const uint4* srcB = reinterpret_cast<const uint4*>(Bimg);
        uint4* dstB = reinterpret_cast<uint4*>(dynsm + 32768);
#pragma unroll
        for (int i = 0; i < 8; ++i) dstB[tid + i * 256] = srcB[tid + i * 256];
    }
    // A: straight swizzled copy (fp16 image, exact)
    {
        const uint4* srcA = reinterpret_cast<const uint4*>(neighh) + (size_t)row0 * 16;
#pragma unroll
        for (int it = 0; it < 8; ++it) {
            int idx = tid + it * 256;
            int r = idx >> 4;
            int u = idx & 15;
            uint4 v = srcA[idx];
            *reinterpret_cast<uint4*>(dynsm + r * 256 + (((u ^ (r & 7))) << 4)) = v;
        }
    }
    __syncthreads();

    GemmCore core;
    core.run(sb, wid, lane);

    const int tg = lane >> 2, tig = lane & 3;
#pragma unroll
    for (int rb = 0; rb < 2; ++rb)
#pragma unroll
        for (int nb = 0; nb < 8; ++nb) {
            float* d = core.acc[rb][nb];
            int c = core.c0w + nb * 8 + tig * 2;
            int r1 = row0 + core.r0w + rb * 16 + tg;
            if (r1 < M)
                *reinterpret_cast<float2*>(C + (size_t)r1 * HD + c) =
                    make_float2(tanhf(d[0]), tanhf(d[1]));
            if (r1 + 8 < M)
                *reinterpret_cast<float2*>(C + (size_t)(r1 + 8) * HD + c) =
                    make_float2(tanhf(d[2]), tanhf(d[3]));
        }
}

// ---------------------------------------------------------------
// Attention: warp per node; rank-based top-k; rank = compaction slot.
// Gather: 16 lanes/neighbor, 2 neighbors/iter via LDG.128.
// ---------------------------------------------------------------
__global__ void __launch_bounds__(256) attn_kernel(const int* __restrict__ src,
                                                   const int* __restrict__ relid) {
    __shared__ __align__(16) float ssc[8][32];
    __shared__ float swgt[8][16];
    __shared__ int spk[8][16];

    int warp = (blockIdx.x * blockDim.x + threadIdx.x) >> 5;
    int w = threadIdx.x >> 5;
    int lane = threadIdx.x & 31;
    if (warp >= NENT) return;
    const int n = warp;

    int s_id = src[(size_t)n * DEG + lane];
    int r_id = relid[(size_t)n * DEG + lane];
    float sc = g_ssrc[s_id] + g_sdst[n] + g_srel[r_id];
    sc = sc > 0.f ? sc : 0.2f * sc;  // leaky_relu 0.2

    ssc[w][lane] = sc;
    __syncwarp();
    int rank = 0;
#pragma unroll
    for (int j4 = 0; j4 < 8; ++j4) {
        float4 q = *reinterpret_cast<const float4*>(&ssc[w][j4 * 4]);
        int j = j4 * 4;
        rank += (q.x > sc) || (q.x == sc && (j + 0) < lane);
        rank += (q.y > sc) || (q.y == sc && (j + 1) < lane);
        rank += (q.z > sc) || (q.z == sc && (j + 2) < lane);
        rank += (q.w > sc) || (q.w == sc && (j + 3) < lane);
    }
    bool sel = rank < TOPK;

    float p = sel ? __expf(sc) : 0.f;
    float s = p;
#pragma unroll
    for (int o = 16; o; o >>= 1) s += __shfl_xor_sync(0xffffffffu, s, o);

    if (sel) {
        swgt[w][rank] = p / s;
        spk[w][rank] = s_id | (r_id << 18);
    }
    __syncwarp();

    const int half = lane >> 4;
    const int j = lane & 15;
    float acc[8];
#pragma unroll
    for (int d = 0; d < 8; ++d) acc[d] = 0.f;

#pragma unroll
    for (int it = 0; it < 5; ++it) {
        int k = it * 2 + half;
        float wgt = swgt[w][k];
        int pks = spk[w][k];
        int sk = pks & 0x3FFFF;
        int rk = pks >> 18;
        uint4 hn = *reinterpret_cast<const uint4*>(g_hnodeh + (size_t)sk * 64 + j * 4);
        uint4 hr = *reinterpret_cast<const uint4*>(g_hrelh + rk * 64 + j * 4);
        float2 f0 = __half22float2(__hadd2(u2h2(hn.x), u2h2(hr.x)));
        float2 f1 = __half22float2(__hadd2(u2h2(hn.y), u2h2(hr.y)));
        float2 f2 = __half22float2(__hadd2(u2h2(hn.z), u2h2(hr.z)));
        float2 f3 = __half22float2(__hadd2(u2h2(hn.w), u2h2(hr.w)));
        acc[0] += wgt * f0.x; acc[1] += wgt * f0.y;
        acc[2] += wgt * f1.x; acc[3] += wgt * f1.y;
        acc[4] += wgt * f2.x; acc[5] += wgt * f2.y;
        acc[6] += wgt * f3.x; acc[7] += wgt * f3.y;
    }

#pragma unroll
    for (int d = 0; d < 8; ++d) acc[d] += __shfl_down_sync(0xffffffffu, acc[d], 16);

    if (lane < 16) {
        uint4 o;
        o.x = pack2(__float2half_rn(acc[0]), __float2half_rn(acc[1]));
        o.y = pack2(__float2half_rn(acc[2]), __float2half_rn(acc[3]));
        o.z = pack2(__float2half_rn(acc[4]), __float2half_rn(acc[5]));
        o.w = pack2(__float2half_rn(acc[6]), __float2half_rn(acc[7]));
        *reinterpret_cast<uint4*>(g_neighh + (size_t)n * 64 + j * 4) = o;
    }
}

// ---------------------------------------------------------------
extern "C" void kernel_launch(void* const* d_in, const int* in_sizes, int n_in,
                              void* d_out, int out_size) {
    const float* ent   = (const float*)d_in[0];
    const float* rel   = (const float*)d_in[1];
    const float* W     = (const float*)d_in[2];
    const float* Wr    = (const float*)d_in[3];
    const float* a     = (const float*)d_in[4];
    const float* nw    = (const float*)d_in[5];
    const int*   src   = (const int*)d_in[6];
    const int*   relid = (const int*)d_in[7];
    float* out = (float*)d_out;

    uint32_t* p_neighh;
    unsigned char* p_img;
    cudaGetSymbolAddress((void**)&p_neighh, g_neighh);
    cudaGetSymbolAddress((void**)&p_img, g_Bimg);

    cudaFuncSetAttribute(gemm_node_rel, cudaFuncAttributeMaxDynamicSharedMemorySize, 65536);
    cudaFuncSetAttribute(gemm_out, cudaFuncAttributeMaxDynamicSharedMemorySize, 65536);

    prep_kernel<<<4, 256>>>(W, Wr, nw, a);

    // h_node + h_rel (fp16 images) + exact fp32 scores, fused (single-pass)
    gemm_node_rel<<<NB + 4, 256, 65536>>>(ent, rel, p_img);
    // attention + aggregation (fp16 gathers, fp16 neigh out)
    attn_kernel<<<(NENT * 32 + 255) / 256, 256>>>(src, relid);
    // out = tanh(neigh @ neigh_w)  (single-pass, 64KB smem)
    gemm_out<<<NB, 256, 65536>>>(p_neighh, p_img + 2 * 65536, out, NENT);
}